// round 2
// baseline (speedup 1.0000x reference)
#include <cuda_runtime.h>
#include <cuda_bf16.h>

#define NN 50000
#define EE 800000
#define CC 512     // H*HID
#define HH 8
#define FF 64

// ---------------- scratch (device globals; no allocation allowed) ----------
__device__ float g_feat[(size_t)NN * CC];   // 102.4 MB projected features
__device__ float g_el[NN * HH];
__device__ float g_er[NN * HH];
__device__ float g_h[NN * FF];              // layer activations (ping in place)
__device__ int   g_rowptr[NN + 1];
__device__ int   g_cnt[NN];
__device__ int   g_fill[NN];
__device__ int   g_col[EE];                 // src ids grouped by dst

// ---------------- CSR build ------------------------------------------------
__global__ void k_zero() {
    int i = blockIdx.x * blockDim.x + threadIdx.x;
    if (i < NN) { g_cnt[i] = 0; g_fill[i] = 0; }
}

__global__ void k_hist(const int* __restrict__ dst) {
    int e = blockIdx.x * blockDim.x + threadIdx.x;
    if (e < EE) atomicAdd(&g_cnt[dst[e]], 1);
}

__global__ void k_scan() {
    __shared__ int sh[1024];
    __shared__ int s_off;
    int tid = threadIdx.x;
    if (tid == 0) s_off = 0;
    __syncthreads();
    for (int base = 0; base < NN; base += 1024) {
        int idx = base + tid;
        int orig = (idx < NN) ? g_cnt[idx] : 0;
        int v = orig;
        sh[tid] = v;
        __syncthreads();
        for (int off = 1; off < 1024; off <<= 1) {
            int add = (tid >= off) ? sh[tid - off] : 0;
            __syncthreads();
            v += add; sh[tid] = v;
            __syncthreads();
        }
        int myoff = s_off;
        if (idx < NN) g_rowptr[idx] = myoff + (v - orig);
        __syncthreads();
        if (tid == 1023) s_off = myoff + v;   // v at tid 1023 = chunk total
        __syncthreads();
    }
    if (tid == 0) g_rowptr[NN] = s_off;
}

__global__ void k_scatter(const int* __restrict__ src, const int* __restrict__ dst) {
    int e = blockIdx.x * blockDim.x + threadIdx.x;
    if (e < EE) {
        int d = dst[e];
        int pos = g_rowptr[d] + atomicAdd(&g_fill[d], 1);
        g_col[pos] = src[e];
    }
}

// ---------------- GEMM: C[M,NCol] = A[M,K] @ B[NCol,K]^T (+bias) -----------
__global__ void k_gemm(const float* __restrict__ A, const float* __restrict__ B,
                       const float* __restrict__ bias, float* __restrict__ C,
                       int M, int NCol, int K) {
    __shared__ float As[16][64];
    __shared__ float Bs[16][64];
    int tid = threadIdx.x;
    int lk = tid & 15, lm = tid >> 4;
    int tx = tid & 15, ty = tid >> 4;
    int m0 = blockIdx.y * 64, c0 = blockIdx.x * 64;
    float acc[4][4] = {};
    for (int kt = 0; kt < K; kt += 16) {
#pragma unroll
        for (int r = 0; r < 4; r++) {
            int row = m0 + lm + 16 * r;
            As[lk][lm + 16 * r] = (row < M) ? A[(size_t)row * K + kt + lk] : 0.f;
            int col = c0 + lm + 16 * r;
            Bs[lk][lm + 16 * r] = (col < NCol) ? B[(size_t)col * K + kt + lk] : 0.f;
        }
        __syncthreads();
#pragma unroll
        for (int kk = 0; kk < 16; kk++) {
            float a[4], bb[4];
#pragma unroll
            for (int i = 0; i < 4; i++) a[i] = As[kk][ty * 4 + i];
#pragma unroll
            for (int j = 0; j < 4; j++) bb[j] = Bs[kk][tx * 4 + j];
#pragma unroll
            for (int i = 0; i < 4; i++)
#pragma unroll
                for (int j = 0; j < 4; j++)
                    acc[i][j] += a[i] * bb[j];
        }
        __syncthreads();
    }
#pragma unroll
    for (int i = 0; i < 4; i++) {
        int row = m0 + ty * 4 + i;
        if (row < M) {
#pragma unroll
            for (int j = 0; j < 4; j++) {
                int col = c0 + tx * 4 + j;
                float v = acc[i][j];
                if (bias) v += bias[col];
                C[(size_t)row * NCol + col] = v;
            }
        }
    }
}

// ---------------- el/er: per-(node,head) dot of feat with al/ar ------------
__global__ void k_eler(const float* __restrict__ al, const float* __restrict__ ar) {
    int n = blockIdx.x;
    int w = threadIdx.x >> 5, lane = threadIdx.x & 31;
    const float* f = g_feat + (size_t)n * CC + w * FF;
    float f0 = f[lane], f1 = f[lane + 32];
    float a0 = al[w * FF + lane], a1 = al[w * FF + lane + 32];
    float r0 = ar[w * FF + lane], r1 = ar[w * FF + lane + 32];
    float sl = f0 * a0 + f1 * a1;
    float sr = f0 * r0 + f1 * r1;
#pragma unroll
    for (int o = 16; o; o >>= 1) {
        sl += __shfl_xor_sync(0xffffffffu, sl, o);
        sr += __shfl_xor_sync(0xffffffffu, sr, o);
    }
    if (lane == 0) { g_el[n * HH + w] = sl; g_er[n * HH + w] = sr; }
}

// ---------------- attention + aggregate: block per dst, warp per head ------
__global__ void k_agg(const float* __restrict__ bias, float* __restrict__ y) {
    int n = blockIdx.x;
    int tid = threadIdx.x, w = tid >> 5, lane = tid & 31;
    __shared__ float s_acc[HH][FF];
    int beg = g_rowptr[n], end = g_rowptr[n + 1];
    int deg = end - beg;
    float erw = g_er[n * HH + w];

    // pass 1: per-head max (warp-local)
    float m = -1e30f;
    for (int i = lane; i < deg; i += 32) {
        int s = g_col[beg + i];
        float e = g_el[s * HH + w] + erw;
        e = e > 0.f ? e : 0.2f * e;
        m = fmaxf(m, e);
    }
#pragma unroll
    for (int o = 16; o; o >>= 1) m = fmaxf(m, __shfl_xor_sync(0xffffffffu, m, o));

    // pass 2: exp-sum + weighted feature accumulation (2 floats/lane)
    float acc0 = 0.f, acc1 = 0.f, ssum = 0.f;
    int k0 = w * FF + lane * 2;
    if (deg > 0) {
        int   sc  = g_col[beg];
        float elc = g_el[sc * HH + w];
        const float* fr = g_feat + (size_t)sc * CC + k0;
        float fa = fr[0], fb = fr[1];
        for (int i = 0; i < deg; i++) {
            int sn = 0; float eln = 0.f, fan = 0.f, fbn = 0.f;
            if (i + 1 < deg) {
                sn  = g_col[beg + i + 1];
                eln = g_el[sn * HH + w];
                const float* fn = g_feat + (size_t)sn * CC + k0;
                fan = fn[0]; fbn = fn[1];
            }
            float e = elc + erw;
            e = e > 0.f ? e : 0.2f * e;
            float p = __expf(e - m);
            acc0 += p * fa; acc1 += p * fb; ssum += p;
            sc = sn; elc = eln; fa = fan; fb = fbn;
        }
    }
    float inv = (deg > 0) ? 1.0f / ssum : 0.f;
    s_acc[w][lane * 2]     = acc0 * inv + bias[k0];
    s_acc[w][lane * 2 + 1] = acc1 * inv + bias[k0 + 1];
    __syncthreads();

    // sum heads + leaky(0.01)
    if (tid < FF) {
        float v = 0.f;
#pragma unroll
        for (int hh = 0; hh < HH; hh++) v += s_acc[hh][tid];
        v = v > 0.f ? v : 0.01f * v;
        y[(size_t)n * FF + tid] = v;
    }
}

// ---------------- launcher -------------------------------------------------
extern "C" void kernel_launch(void* const* d_in, const int* in_sizes, int n_in,
                              void* d_out, int out_size) {
    const float* x   = (const float*)d_in[0];
    const int*   src = (const int*)d_in[1];
    const int*   dst = (const int*)d_in[2];
    const float* W1  = (const float*)d_in[3];
    const float* al1 = (const float*)d_in[4];
    const float* ar1 = (const float*)d_in[5];
    const float* b1  = (const float*)d_in[6];
    const float* W2  = (const float*)d_in[7];
    const float* al2 = (const float*)d_in[8];
    const float* ar2 = (const float*)d_in[9];
    const float* b2  = (const float*)d_in[10];
    const float* W3  = (const float*)d_in[11];
    const float* al3 = (const float*)d_in[12];
    const float* ar3 = (const float*)d_in[13];
    const float* b3  = (const float*)d_in[14];
    const float* Wm  = (const float*)d_in[15];
    const float* bm  = (const float*)d_in[16];
    float* out = (float*)d_out;

    float *feat_p, *h_p;
    cudaGetSymbolAddress((void**)&feat_p, g_feat);
    cudaGetSymbolAddress((void**)&h_p, g_h);

    // CSR by dst (rebuilt every call; identical work each time)
    k_zero<<<(NN + 255) / 256, 256>>>();
    k_hist<<<(EE + 255) / 256, 256>>>(dst);
    k_scan<<<1, 1024>>>();
    k_scatter<<<(EE + 255) / 256, 256>>>(src, dst);

    dim3 gemm_grid_proj(CC / 64, (NN + 63) / 64);

    // layer 1 (K=128)
    k_gemm<<<gemm_grid_proj, 256>>>(x, W1, nullptr, feat_p, NN, CC, 128);
    k_eler<<<NN, 256>>>(al1, ar1);
    k_agg<<<NN, 256>>>(b1, h_p);

    // layer 2 (K=64)
    k_gemm<<<gemm_grid_proj, 256>>>(h_p, W2, nullptr, feat_p, NN, CC, 64);
    k_eler<<<NN, 256>>>(al2, ar2);
    k_agg<<<NN, 256>>>(b2, h_p);

    // layer 3 (K=64)
    k_gemm<<<gemm_grid_proj, 256>>>(h_p, W3, nullptr, feat_p, NN, CC, 64);
    k_eler<<<NN, 256>>>(al3, ar3);
    k_agg<<<NN, 256>>>(b3, h_p);

    // final linear: out = h @ Wm^T + bm  [N,64]
    k_gemm<<<dim3(1, (NN + 63) / 64), 256>>>(h_p, Wm, bm, out, NN, FF, FF);
}

// round 3
// speedup vs baseline: 1.3611x; 1.3611x over previous
#include <cuda_runtime.h>
#include <cuda_bf16.h>
#include <cstdint>

#define NN 50000
#define EE 800000
#define CC 512     // H*HID
#define HH 8
#define FF 64

// ---------------- scratch (device globals; no allocation allowed) ----------
__device__ float g_feat[(size_t)NN * CC];   // 102.4 MB projected features
__device__ float g_el[NN * HH];
__device__ float g_er[NN * HH];
__device__ float g_h[NN * FF];              // layer activations
__device__ int   g_rowptr[NN + 1];
__device__ int   g_cnt[NN];
__device__ int   g_fill[NN];
__device__ int   g_col[EE];                 // src ids grouped by dst

// ---------------- CSR build ------------------------------------------------
__global__ void k_zero() {
    int i = blockIdx.x * blockDim.x + threadIdx.x;
    if (i < NN) { g_cnt[i] = 0; g_fill[i] = 0; }
}

__global__ void k_hist(const int* __restrict__ dst) {
    int e = blockIdx.x * blockDim.x + threadIdx.x;
    if (e < EE) atomicAdd(&g_cnt[dst[e]], 1);
}

__global__ void k_scan() {
    __shared__ int sh[1024];
    __shared__ int s_off;
    int tid = threadIdx.x;
    if (tid == 0) s_off = 0;
    __syncthreads();
    for (int base = 0; base < NN; base += 1024) {
        int idx = base + tid;
        int orig = (idx < NN) ? g_cnt[idx] : 0;
        int v = orig;
        sh[tid] = v;
        __syncthreads();
        for (int off = 1; off < 1024; off <<= 1) {
            int add = (tid >= off) ? sh[tid - off] : 0;
            __syncthreads();
            v += add; sh[tid] = v;
            __syncthreads();
        }
        int myoff = s_off;
        if (idx < NN) g_rowptr[idx] = myoff + (v - orig);
        __syncthreads();
        if (tid == 1023) s_off = myoff + v;
        __syncthreads();
    }
    if (tid == 0) g_rowptr[NN] = s_off;
}

__global__ void k_scatter(const int* __restrict__ src, const int* __restrict__ dst) {
    int e = blockIdx.x * blockDim.x + threadIdx.x;
    if (e < EE) {
        int d = dst[e];
        int pos = g_rowptr[d] + atomicAdd(&g_fill[d], 1);
        g_col[pos] = src[e];
    }
}

// ---------------- tf32 tensor-core GEMM ------------------------------------
// C[M,NCol] = A[M,K] @ B[NCol,K]^T (+bias).  K multiple of 32, NCol mult of 64.
__device__ __forceinline__ uint32_t f2tf(float f) {
    uint32_t r;
    asm("cvt.rna.tf32.f32 %0, %1;" : "=r"(r) : "f"(f));
    return r;
}

__global__ __launch_bounds__(256, 2) void k_gemm_tc(
    const float* __restrict__ A, const float* __restrict__ B,
    const float* __restrict__ bias, float* __restrict__ C,
    int M, int NCol, int K)
{
    // fragment-layout smem: [kstep(4)][tile(8)][lane(32)][quad]
    __shared__ uint32_t As2[4 * 8 * 32 * 4];   // 16 KB
    __shared__ uint32_t Bs2[4 * 8 * 32 * 2];   //  8 KB
    const int tid = threadIdx.x;
    const int lane = tid & 31, wid = tid >> 5;
    const int wm = wid & 3, wn = wid >> 2;          // warp grid 4(M) x 2(N)
    const int m0 = blockIdx.y * 128, n0 = blockIdx.x * 64;

    float acc[2][4][4];
#pragma unroll
    for (int im = 0; im < 2; im++)
#pragma unroll
        for (int in = 0; in < 4; in++)
#pragma unroll
            for (int q = 0; q < 4; q++) acc[im][in][q] = 0.f;

    float4 rA[4], rB[2];

    // prefetch slab 0
#pragma unroll
    for (int i = 0; i < 4; i++) {
        int idx = tid + 256 * i;
        int row = idx >> 3, c0 = (idx & 7) << 2;
        int gr = m0 + row;
        rA[i] = (gr < M) ? *(const float4*)(A + (size_t)gr * K + c0)
                         : make_float4(0.f, 0.f, 0.f, 0.f);
    }
#pragma unroll
    for (int i = 0; i < 2; i++) {
        int idx = tid + 256 * i;
        int row = idx >> 3, c0 = (idx & 7) << 2;
        rB[i] = *(const float4*)(B + (size_t)(n0 + row) * K + c0);
    }

    for (int kt = 0; kt < K; kt += 32) {
        __syncthreads();   // previous compute done; safe to overwrite smem
        // ---- store A fragments (pre-permuted, tf32-converted) ----
#pragma unroll
        for (int i = 0; i < 4; i++) {
            int idx = tid + 256 * i;
            int row = idx >> 3, c0 = (idx & 7) << 2;
            int mt = row >> 4, rr = row & 15;
            int q1 = rr >> 3, lrow = rr & 7;
            int ks = c0 >> 3, q0 = (c0 >> 2) & 1;
            int quad = q1 * 2 + q0;
            int base = (ks * 8 + mt) * 32;
            int lb = lrow * 4 + ks * 8;
            As2[(base + ((lb + 0) & 31)) * 4 + quad] = f2tf(rA[i].x);
            As2[(base + ((lb + 1) & 31)) * 4 + quad] = f2tf(rA[i].y);
            As2[(base + ((lb + 2) & 31)) * 4 + quad] = f2tf(rA[i].z);
            As2[(base + ((lb + 3) & 31)) * 4 + quad] = f2tf(rA[i].w);
        }
        // ---- store B fragments ----
#pragma unroll
        for (int i = 0; i < 2; i++) {
            int idx = tid + 256 * i;
            int row = idx >> 3, c0 = (idx & 7) << 2;
            int nt = row >> 3, ln = row & 7;
            int ks = c0 >> 3, q0 = (c0 >> 2) & 1;
            int base = (ks * 8 + nt) * 32;
            int lb = ln * 4 + ks * 8;
            Bs2[(base + ((lb + 0) & 31)) * 2 + q0] = f2tf(rB[i].x);
            Bs2[(base + ((lb + 1) & 31)) * 2 + q0] = f2tf(rB[i].y);
            Bs2[(base + ((lb + 2) & 31)) * 2 + q0] = f2tf(rB[i].z);
            Bs2[(base + ((lb + 3) & 31)) * 2 + q0] = f2tf(rB[i].w);
        }
        __syncthreads();

        // ---- prefetch next slab (overlaps with mma below) ----
        if (kt + 32 < K) {
#pragma unroll
            for (int i = 0; i < 4; i++) {
                int idx = tid + 256 * i;
                int row = idx >> 3, c0 = (idx & 7) << 2;
                int gr = m0 + row;
                rA[i] = (gr < M) ? *(const float4*)(A + (size_t)gr * K + kt + 32 + c0)
                                 : make_float4(0.f, 0.f, 0.f, 0.f);
            }
#pragma unroll
            for (int i = 0; i < 2; i++) {
                int idx = tid + 256 * i;
                int row = idx >> 3, c0 = (idx & 7) << 2;
                rB[i] = *(const float4*)(B + (size_t)(n0 + row) * K + kt + 32 + c0);
            }
        }

        // ---- compute: 4 k-steps x 8 mma per warp ----
#pragma unroll
        for (int ks = 0; ks < 4; ks++) {
            int ll = (lane + ks * 8) & 31;
            uint32_t a[2][4];
#pragma unroll
            for (int im = 0; im < 2; im++) {
                uint4 v = *(const uint4*)(As2 + ((ks * 8 + wm * 2 + im) * 32 + ll) * 4);
                a[im][0] = v.x; a[im][2] = v.y; a[im][1] = v.z; a[im][3] = v.w;
            }
            uint32_t b[4][2];
#pragma unroll
            for (int in = 0; in < 4; in++) {
                uint2 v = *(const uint2*)(Bs2 + ((ks * 8 + wn * 4 + in) * 32 + ll) * 2);
                b[in][0] = v.x; b[in][1] = v.y;
            }
#pragma unroll
            for (int im = 0; im < 2; im++)
#pragma unroll
                for (int in = 0; in < 4; in++)
                    asm volatile(
                        "mma.sync.aligned.m16n8k8.row.col.f32.tf32.tf32.f32 "
                        "{%0,%1,%2,%3},{%4,%5,%6,%7},{%8,%9},{%0,%1,%2,%3};"
                        : "+f"(acc[im][in][0]), "+f"(acc[im][in][1]),
                          "+f"(acc[im][in][2]), "+f"(acc[im][in][3])
                        : "r"(a[im][0]), "r"(a[im][1]), "r"(a[im][2]), "r"(a[im][3]),
                          "r"(b[in][0]), "r"(b[in][1]));
        }
    }

    // ---- epilogue ----
    int gid = lane >> 2, tig = lane & 3;
#pragma unroll
    for (int im = 0; im < 2; im++) {
        int r = m0 + wm * 32 + im * 16 + gid;
#pragma unroll
        for (int in = 0; in < 4; in++) {
            int c = n0 + wn * 32 + in * 8 + tig * 2;
            float b0v = bias ? bias[c] : 0.f;
            float b1v = bias ? bias[c + 1] : 0.f;
            if (r < M) {
                C[(size_t)r * NCol + c]     = acc[im][in][0] + b0v;
                C[(size_t)r * NCol + c + 1] = acc[im][in][1] + b1v;
            }
            if (r + 8 < M) {
                C[(size_t)(r + 8) * NCol + c]     = acc[im][in][2] + b0v;
                C[(size_t)(r + 8) * NCol + c + 1] = acc[im][in][3] + b1v;
            }
        }
    }
}

// ---------------- el/er: per-(node,head) dot of feat with al/ar ------------
__global__ void k_eler(const float* __restrict__ al, const float* __restrict__ ar) {
    int n = blockIdx.x;
    int w = threadIdx.x >> 5, lane = threadIdx.x & 31;
    const float* f = g_feat + (size_t)n * CC + w * FF;
    float f0 = f[lane], f1 = f[lane + 32];
    float a0 = al[w * FF + lane], a1 = al[w * FF + lane + 32];
    float r0 = ar[w * FF + lane], r1 = ar[w * FF + lane + 32];
    float sl = f0 * a0 + f1 * a1;
    float sr = f0 * r0 + f1 * r1;
#pragma unroll
    for (int o = 16; o; o >>= 1) {
        sl += __shfl_xor_sync(0xffffffffu, sl, o);
        sr += __shfl_xor_sync(0xffffffffu, sr, o);
    }
    if (lane == 0) { g_el[n * HH + w] = sl; g_er[n * HH + w] = sr; }
}

// ---------------- attention + aggregate: block per dst, warp per head ------
__global__ void k_agg(const float* __restrict__ bias, float* __restrict__ y) {
    int n = blockIdx.x;
    int tid = threadIdx.x, w = tid >> 5, lane = tid & 31;
    __shared__ float s_acc[HH][FF];
    int beg = g_rowptr[n], end = g_rowptr[n + 1];
    int deg = end - beg;
    float erw = g_er[n * HH + w];

    // pass 1: per-head max (warp-local)
    float m = -1e30f;
    for (int i = lane; i < deg; i += 32) {
        int s = g_col[beg + i];
        float e = g_el[s * HH + w] + erw;
        e = e > 0.f ? e : 0.2f * e;
        m = fmaxf(m, e);
    }
#pragma unroll
    for (int o = 16; o; o >>= 1) m = fmaxf(m, __shfl_xor_sync(0xffffffffu, m, o));

    // pass 2: exp-sum + weighted feature accumulation (2 floats/lane)
    float acc0 = 0.f, acc1 = 0.f, ssum = 0.f;
    int k0 = w * FF + lane * 2;
    if (deg > 0) {
        int   sc  = g_col[beg];
        float elc = g_el[sc * HH + w];
        const float* fr = g_feat + (size_t)sc * CC + k0;
        float fa = fr[0], fb = fr[1];
        for (int i = 0; i < deg; i++) {
            int sn = 0; float eln = 0.f, fan = 0.f, fbn = 0.f;
            if (i + 1 < deg) {
                sn  = g_col[beg + i + 1];
                eln = g_el[sn * HH + w];
                const float* fn = g_feat + (size_t)sn * CC + k0;
                fan = fn[0]; fbn = fn[1];
            }
            float e = elc + erw;
            e = e > 0.f ? e : 0.2f * e;
            float p = __expf(e - m);
            acc0 += p * fa; acc1 += p * fb; ssum += p;
            sc = sn; elc = eln; fa = fan; fb = fbn;
        }
    }
    float inv = (deg > 0) ? 1.0f / ssum : 0.f;
    s_acc[w][lane * 2]     = acc0 * inv + bias[k0];
    s_acc[w][lane * 2 + 1] = acc1 * inv + bias[k0 + 1];
    __syncthreads();

    // sum heads + leaky(0.01)
    if (tid < FF) {
        float v = 0.f;
#pragma unroll
        for (int hh = 0; hh < HH; hh++) v += s_acc[hh][tid];
        v = v > 0.f ? v : 0.01f * v;
        y[(size_t)n * FF + tid] = v;
    }
}

// ---------------- launcher -------------------------------------------------
extern "C" void kernel_launch(void* const* d_in, const int* in_sizes, int n_in,
                              void* d_out, int out_size) {
    const float* x   = (const float*)d_in[0];
    const int*   src = (const int*)d_in[1];
    const int*   dst = (const int*)d_in[2];
    const float* W1  = (const float*)d_in[3];
    const float* al1 = (const float*)d_in[4];
    const float* ar1 = (const float*)d_in[5];
    const float* b1  = (const float*)d_in[6];
    const float* W2  = (const float*)d_in[7];
    const float* al2 = (const float*)d_in[8];
    const float* ar2 = (const float*)d_in[9];
    const float* b2  = (const float*)d_in[10];
    const float* W3  = (const float*)d_in[11];
    const float* al3 = (const float*)d_in[12];
    const float* ar3 = (const float*)d_in[13];
    const float* b3  = (const float*)d_in[14];
    const float* Wm  = (const float*)d_in[15];
    const float* bm  = (const float*)d_in[16];
    float* out = (float*)d_out;

    float *feat_p, *h_p;
    cudaGetSymbolAddress((void**)&feat_p, g_feat);
    cudaGetSymbolAddress((void**)&h_p, g_h);

    // CSR by dst (rebuilt every call; identical work each time)
    k_zero<<<(NN + 255) / 256, 256>>>();
    k_hist<<<(EE + 255) / 256, 256>>>(dst);
    k_scan<<<1, 1024>>>();
    k_scatter<<<(EE + 255) / 256, 256>>>(src, dst);

    dim3 gproj(CC / 64, (NN + 127) / 128);

    // layer 1 (K=128)
    k_gemm_tc<<<gproj, 256>>>(x, W1, nullptr, feat_p, NN, CC, 128);
    k_eler<<<NN, 256>>>(al1, ar1);
    k_agg<<<NN, 256>>>(b1, h_p);

    // layer 2 (K=64)
    k_gemm_tc<<<gproj, 256>>>(h_p, W2, nullptr, feat_p, NN, CC, 64);
    k_eler<<<NN, 256>>>(al2, ar2);
    k_agg<<<NN, 256>>>(b2, h_p);

    // layer 3 (K=64)
    k_gemm_tc<<<gproj, 256>>>(h_p, W3, nullptr, feat_p, NN, CC, 64);
    k_eler<<<NN, 256>>>(al3, ar3);
    k_agg<<<NN, 256>>>(b3, h_p);

    // final linear: out = h @ Wm^T + bm  [N,64]
    k_gemm_tc<<<dim3(1, (NN + 127) / 128), 256>>>(h_p, Wm, bm, out, NN, FF, FF);
}